// round 4
// baseline (speedup 1.0000x reference)
#include <cuda_runtime.h>

// Problem constants
#define NB   8
#define NS   1024
#define ND   1024
#define NH   16
#define NHD  64
#define MROWS (NB * NS)   // 8192

// ---------------------------------------------------------------------------
// Device scratch (allocation-free rule: __device__ globals)
// ---------------------------------------------------------------------------
__device__ float g_q[(size_t)MROWS * ND];
__device__ float g_k[(size_t)MROWS * ND];
__device__ float g_v[(size_t)MROWS * ND];
__device__ float g_o[(size_t)MROWS * ND];
__device__ float g_x[(size_t)MROWS * ND];
__device__ float g_bias[MROWS];           // additive mask bias per (b, key)

// ---------------------------------------------------------------------------
// Mask conversion: robust to int32 / float32 / byte-bool encodings.
// Heuristic: inspect the first 2048 32-bit words (safe in-bounds for all
// encodings). Random 0/1 byte-bools cannot all form words in {0,1} nor
// {0, 0x3F800000}; int32 0/1 masks form only {0,1}; float 0/1 masks form
// only {0, 0x3F800000}. Deterministic given the input.
// ---------------------------------------------------------------------------
__global__ void mask_convert(const void* __restrict__ mask) {
    __shared__ int flag_not01;
    __shared__ int flag_notfp;
    if (threadIdx.x == 0) { flag_not01 = 0; flag_notfp = 0; }
    __syncthreads();
    const unsigned* w = (const unsigned*)mask;
    for (int i = threadIdx.x; i < 2048; i += blockDim.x) {
        unsigned v = w[i];
        if (v > 1u) flag_not01 = 1;
        if (v != 0u && v != 0x3F800000u) flag_notfp = 1;
    }
    __syncthreads();
    const int mode = (flag_not01 == 0) ? 0 : ((flag_notfp == 0) ? 1 : 2);
    for (int i = threadIdx.x; i < MROWS; i += blockDim.x) {
        bool on;
        if (mode == 0)      on = ((const int*)mask)[i] != 0;
        else if (mode == 1) on = ((const float*)mask)[i] != 0.0f;
        else                on = ((const unsigned char*)mask)[i] != 0;
        g_bias[i] = on ? -1e9f : 0.0f;
    }
}

// ---------------------------------------------------------------------------
// SGEMM (NT): C[m,n] = sum_k A[m,k] * W[n,k] + bias[n] (+ res[m,n])
// A: [8192,1024], W: [1024,1024], tiles 128x128x8, 256 threads, 8x8/thread.
// MODE selects scratch-global source/dest (avoids host symbol lookups).
// ---------------------------------------------------------------------------
#define GM_TO_Q 0
#define GM_TO_K 1
#define GM_TO_V 2
#define GM_PROJ 3

template <int MODE>
__global__ __launch_bounds__(256, 2) void sgemm_nt(
    const float* __restrict__ Ain, const float* __restrict__ W,
    const float* __restrict__ bias, const float* __restrict__ res_y)
{
    const float* A = (MODE == GM_PROJ) ? g_o : Ain;
    float* C = (MODE == GM_TO_Q) ? g_q
             : (MODE == GM_TO_K) ? g_k
             : (MODE == GM_TO_V) ? g_v : g_x;

    __shared__ float As[8][128];
    __shared__ float Bs[8][128];

    const int tid  = threadIdx.x;
    const int row0 = blockIdx.y * 128;
    const int col0 = blockIdx.x * 128;
    const int tx   = tid & 15;
    const int ty   = tid >> 4;
    const int lr   = tid >> 1;
    const int lk   = (tid & 1) << 2;

    const float* Ag = A + (size_t)(row0 + lr) * ND + lk;
    const float* Wg = W + (size_t)(col0 + lr) * ND + lk;

    float4 a4 = *(const float4*)Ag;
    float4 b4 = *(const float4*)Wg;

    float acc[8][8];
#pragma unroll
    for (int i = 0; i < 8; ++i)
#pragma unroll
        for (int j = 0; j < 8; ++j) acc[i][j] = 0.0f;

#pragma unroll 1
    for (int kt = 0; kt < 128; ++kt) {
        As[lk + 0][lr] = a4.x; As[lk + 1][lr] = a4.y;
        As[lk + 2][lr] = a4.z; As[lk + 3][lr] = a4.w;
        Bs[lk + 0][lr] = b4.x; Bs[lk + 1][lr] = b4.y;
        Bs[lk + 2][lr] = b4.z; Bs[lk + 3][lr] = b4.w;
        __syncthreads();
        if (kt < 127) {
            a4 = *(const float4*)(Ag + (size_t)(kt + 1) * 8);
            b4 = *(const float4*)(Wg + (size_t)(kt + 1) * 8);
        }
#pragma unroll
        for (int kk = 0; kk < 8; ++kk) {
            float ra[8], rb[8];
            *(float4*)(ra + 0) = *(const float4*)&As[kk][8 * ty];
            *(float4*)(ra + 4) = *(const float4*)&As[kk][8 * ty + 4];
            *(float4*)(rb + 0) = *(const float4*)&Bs[kk][8 * tx];
            *(float4*)(rb + 4) = *(const float4*)&Bs[kk][8 * tx + 4];
#pragma unroll
            for (int i = 0; i < 8; ++i)
#pragma unroll
                for (int j = 0; j < 8; ++j)
                    acc[i][j] = fmaf(ra[i], rb[j], acc[i][j]);
        }
        __syncthreads();
    }

    float bj[8];
    *(float4*)(bj + 0) = *(const float4*)&bias[col0 + 8 * tx];
    *(float4*)(bj + 4) = *(const float4*)&bias[col0 + 8 * tx + 4];

#pragma unroll
    for (int i = 0; i < 8; ++i) {
        const int r = row0 + 8 * ty + i;
        float* cp = C + (size_t)r * ND + col0 + 8 * tx;
        float4 o0 = make_float4(acc[i][0] + bj[0], acc[i][1] + bj[1],
                                acc[i][2] + bj[2], acc[i][3] + bj[3]);
        float4 o1 = make_float4(acc[i][4] + bj[4], acc[i][5] + bj[5],
                                acc[i][6] + bj[6], acc[i][7] + bj[7]);
        if (MODE == GM_PROJ) {
            const float* rp = res_y + (size_t)r * ND + col0 + 8 * tx;
            float4 r0 = *(const float4*)rp;
            float4 r1 = *(const float4*)(rp + 4);
            o0.x += r0.x; o0.y += r0.y; o0.z += r0.z; o0.w += r0.w;
            o1.x += r1.x; o1.y += r1.y; o1.z += r1.z; o1.w += r1.w;
        }
        *(float4*)cp       = o0;
        *(float4*)(cp + 4) = o1;
    }
}

// ---------------------------------------------------------------------------
// Flash attention: one CTA per (64 q-rows, head). BM=64, BN=32, HD=64.
// 256 threads. Online softmax with running max/sum. Static smem 43.7KB.
// ---------------------------------------------------------------------------
__global__ __launch_bounds__(256) void attn_kernel()
{
    __shared__ float Qs[64][64];     // q rows (pre-scaled by 1/8)
    __shared__ float Kst[64][36];    // K transposed: [hd][key], pad 36
    __shared__ float Vs[32][64];     // [key][hd]
    __shared__ float Ps[64][36];     // scores -> probabilities, pad 36
    __shared__ float m_s[64], l_s[64], al_s[64];

    const int tid = threadIdx.x;
    const int b   = blockIdx.y >> 4;
    const int h   = blockIdx.y & 15;
    const int q0  = blockIdx.x << 6;

    // Load Q tile, scaled by 1/sqrt(HD) = 0.125
    {
        const int r  = tid >> 2;
        const int c0 = (tid & 3) << 4;
        const float* src = g_q + ((size_t)(b * 1024 + q0 + r) << 10) + (h << 6) + c0;
#pragma unroll
        for (int u = 0; u < 4; ++u) {
            float4 v = *(const float4*)(src + 4 * u);
            v.x *= 0.125f; v.y *= 0.125f; v.z *= 0.125f; v.w *= 0.125f;
            *(float4*)&Qs[r][c0 + 4 * u] = v;
        }
    }
    if (tid < 64) { m_s[tid] = -1e30f; l_s[tid] = 0.0f; }

    const int pr = (tid >> 3) << 1;   // 2 rows per thread: pr, pr+1
    const int sc = (tid & 7) << 2;    // S-tile cols (4 per thread)
    const int pc = (tid & 7) << 3;    // O-tile cols (8 per thread)

    float Or[2][8];
#pragma unroll
    for (int j = 0; j < 8; ++j) { Or[0][j] = 0.0f; Or[1][j] = 0.0f; }

    const size_t kvbase = ((size_t)b << 20) + (size_t)(h << 6);

    for (int kc = 0; kc < 32; ++kc) {
        const int key0 = kc << 5;
        __syncthreads();   // protect Kst/Vs/Ps from previous chunk's readers
        {
            const int key = tid >> 3;            // 0..31
            const int hd0 = (tid & 7) << 3;      // 0..56
            const float* kp = g_k + kvbase + ((size_t)(key0 + key) << 10) + hd0;
            float4 k1 = *(const float4*)kp;
            float4 k2 = *(const float4*)(kp + 4);
            Kst[hd0 + 0][key] = k1.x; Kst[hd0 + 1][key] = k1.y;
            Kst[hd0 + 2][key] = k1.z; Kst[hd0 + 3][key] = k1.w;
            Kst[hd0 + 4][key] = k2.x; Kst[hd0 + 5][key] = k2.y;
            Kst[hd0 + 6][key] = k2.z; Kst[hd0 + 7][key] = k2.w;
            const float* vp = g_v + kvbase + ((size_t)(key0 + key) << 10) + hd0;
            *(float4*)&Vs[key][hd0]     = *(const float4*)vp;
            *(float4*)&Vs[key][hd0 + 4] = *(const float4*)(vp + 4);
        }
        __syncthreads();

        // S = Q @ K^T  (2x4 per thread)
        float s[2][4] = {{0, 0, 0, 0}, {0, 0, 0, 0}};
#pragma unroll 8
        for (int d = 0; d < 64; ++d) {
            const float qa = Qs[pr][d];
            const float qb = Qs[pr + 1][d];
            const float4 kv = *(const float4*)&Kst[d][sc];
            s[0][0] = fmaf(qa, kv.x, s[0][0]);
            s[0][1] = fmaf(qa, kv.y, s[0][1]);
            s[0][2] = fmaf(qa, kv.z, s[0][2]);
            s[0][3] = fmaf(qa, kv.w, s[0][3]);
            s[1][0] = fmaf(qb, kv.x, s[1][0]);
            s[1][1] = fmaf(qb, kv.y, s[1][1]);
            s[1][2] = fmaf(qb, kv.z, s[1][2]);
            s[1][3] = fmaf(qb, kv.w, s[1][3]);
        }
        const float4 bb = *(const float4*)&g_bias[(b << 10) + key0 + sc];
        s[0][0] += bb.x; s[0][1] += bb.y; s[0][2] += bb.z; s[0][3] += bb.w;
        s[1][0] += bb.x; s[1][1] += bb.y; s[1][2] += bb.z; s[1][3] += bb.w;
        *(float4*)&Ps[pr][sc]     = make_float4(s[0][0], s[0][1], s[0][2], s[0][3]);
        *(float4*)&Ps[pr + 1][sc] = make_float4(s[1][0], s[1][1], s[1][2], s[1][3]);
        __syncthreads();

        // Online softmax statistics: 4 threads per row, 8 cols each
        {
            const int row = tid >> 2;
            const int j0  = (tid & 3) << 3;
            float mx = -1e30f;
#pragma unroll
            for (int j = 0; j < 8; ++j) mx = fmaxf(mx, Ps[row][j0 + j]);
            mx = fmaxf(mx, __shfl_xor_sync(0xffffffffu, mx, 1));
            mx = fmaxf(mx, __shfl_xor_sync(0xffffffffu, mx, 2));
            const float mo = m_s[row];
            const float nm = fmaxf(mo, mx);
            float sm = 0.0f;
#pragma unroll
            for (int j = 0; j < 8; ++j) {
                const float p = __expf(Ps[row][j0 + j] - nm);
                Ps[row][j0 + j] = p;
                sm += p;
            }
            sm += __shfl_xor_sync(0xffffffffu, sm, 1);
            sm += __shfl_xor_sync(0xffffffffu, sm, 2);
            if ((tid & 3) == 0) {
                const float al = __expf(mo - nm);
                l_s[row]  = l_s[row] * al + sm;
                m_s[row]  = nm;
                al_s[row] = al;
            }
        }
        __syncthreads();

        // O = O*alpha + P @ V  (2x8 per thread)
        {
            const float a0 = al_s[pr];
            const float a1 = al_s[pr + 1];
#pragma unroll
            for (int j = 0; j < 8; ++j) { Or[0][j] *= a0; Or[1][j] *= a1; }
#pragma unroll 8
            for (int kx = 0; kx < 32; ++kx) {
                const float p0 = Ps[pr][kx];
                const float p1 = Ps[pr + 1][kx];
                const float4 v1 = *(const float4*)&Vs[kx][pc];
                const float4 v2 = *(const float4*)&Vs[kx][pc + 4];
                Or[0][0] = fmaf(p0, v1.x, Or[0][0]);
                Or[0][1] = fmaf(p0, v1.y, Or[0][1]);
                Or[0][2] = fmaf(p0, v1.z, Or[0][2]);
                Or[0][3] = fmaf(p0, v1.w, Or[0][3]);
                Or[0][4] = fmaf(p0, v2.x, Or[0][4]);
                Or[0][5] = fmaf(p0, v2.y, Or[0][5]);
                Or[0][6] = fmaf(p0, v2.z, Or[0][6]);
                Or[0][7] = fmaf(p0, v2.w, Or[0][7]);
                Or[1][0] = fmaf(p1, v1.x, Or[1][0]);
                Or[1][1] = fmaf(p1, v1.y, Or[1][1]);
                Or[1][2] = fmaf(p1, v1.z, Or[1][2]);
                Or[1][3] = fmaf(p1, v1.w, Or[1][3]);
                Or[1][4] = fmaf(p1, v2.x, Or[1][4]);
                Or[1][5] = fmaf(p1, v2.y, Or[1][5]);
                Or[1][6] = fmaf(p1, v2.z, Or[1][6]);
                Or[1][7] = fmaf(p1, v2.w, Or[1][7]);
            }
        }
    }

    const float r0 = 1.0f / l_s[pr];
    const float r1 = 1.0f / l_s[pr + 1];
    float* op0 = g_o + ((size_t)(b * 1024 + q0 + pr) << 10) + (h << 6) + pc;
    float* op1 = op0 + ND;
    *(float4*)op0       = make_float4(Or[0][0] * r0, Or[0][1] * r0, Or[0][2] * r0, Or[0][3] * r0);
    *(float4*)(op0 + 4) = make_float4(Or[0][4] * r0, Or[0][5] * r0, Or[0][6] * r0, Or[0][7] * r0);
    *(float4*)op1       = make_float4(Or[1][0] * r1, Or[1][1] * r1, Or[1][2] * r1, Or[1][3] * r1);
    *(float4*)(op1 + 4) = make_float4(Or[1][4] * r1, Or[1][5] * r1, Or[1][6] * r1, Or[1][7] * r1);
}

// ---------------------------------------------------------------------------
// LayerNorm (torch semantics): unbiased std (ddof=1), eps added to std.
// One block per row; 256 threads x float4.
// ---------------------------------------------------------------------------
__global__ __launch_bounds__(256) void ln_kernel(
    const float* __restrict__ a2, const float* __restrict__ b2,
    float* __restrict__ out)
{
    const int row = blockIdx.x;
    const int tid = threadIdx.x;
    const float* xr = g_x + (size_t)row * ND;
    const float4 v = *(const float4*)(xr + 4 * tid);

    float s  = v.x + v.y + v.z + v.w;
    float sq = v.x * v.x + v.y * v.y + v.z * v.z + v.w * v.w;
#pragma unroll
    for (int o = 16; o > 0; o >>= 1) {
        s  += __shfl_xor_sync(0xffffffffu, s, o);
        sq += __shfl_xor_sync(0xffffffffu, sq, o);
    }
    __shared__ float sh_s[8], sh_q[8];
    const int w = tid >> 5, ln = tid & 31;
    if (ln == 0) { sh_s[w] = s; sh_q[w] = sq; }
    __syncthreads();
    if (w == 0) {
        s  = (ln < 8) ? sh_s[ln] : 0.0f;
        sq = (ln < 8) ? sh_q[ln] : 0.0f;
#pragma unroll
        for (int o = 4; o > 0; o >>= 1) {
            s  += __shfl_xor_sync(0xffffffffu, s, o);
            sq += __shfl_xor_sync(0xffffffffu, sq, o);
        }
        if (ln == 0) { sh_s[0] = s; sh_q[0] = sq; }
    }
    __syncthreads();
    s  = sh_s[0];
    sq = sh_q[0];

    const float mean = s * (1.0f / 1024.0f);
    const float var  = (sq - s * mean) * (1.0f / 1023.0f);
    const float inv  = 1.0f / (sqrtf(fmaxf(var, 0.0f)) + 1e-6f);

    const float4 av = *(const float4*)(a2 + 4 * tid);
    const float4 bv = *(const float4*)(b2 + 4 * tid);
    float4 o;
    o.x = av.x * (v.x - mean) * inv + bv.x;
    o.y = av.y * (v.y - mean) * inv + bv.y;
    o.z = av.z * (v.z - mean) * inv + bv.z;
    o.w = av.w * (v.w - mean) * inv + bv.w;
    *(float4*)(out + (size_t)row * ND + 4 * tid) = o;
}

// ---------------------------------------------------------------------------
// Launch
// ---------------------------------------------------------------------------
extern "C" void kernel_launch(void* const* d_in, const int* in_sizes, int n_in,
                              void* d_out, int out_size)
{
    const float* y  = (const float*)d_in[0];
    const void*  mk = d_in[1];
    const float* Wq = (const float*)d_in[2];
    const float* bq = (const float*)d_in[3];
    const float* Wk = (const float*)d_in[4];
    const float* bk = (const float*)d_in[5];
    const float* Wv = (const float*)d_in[6];
    const float* bv = (const float*)d_in[7];
    const float* Wm = (const float*)d_in[8];
    const float* bm = (const float*)d_in[9];
    const float* a2 = (const float*)d_in[10];
    const float* b2 = (const float*)d_in[11];
    float* out = (float*)d_out;

    mask_convert<<<1, 256>>>(mk);

    const dim3 gg(ND / 128, MROWS / 128);   // (8, 64)
    sgemm_nt<GM_TO_Q><<<gg, 256>>>(y, Wq, bq, nullptr);
    sgemm_nt<GM_TO_K><<<gg, 256>>>(y, Wk, bk, nullptr);
    sgemm_nt<GM_TO_V><<<gg, 256>>>(y, Wv, bv, nullptr);

    attn_kernel<<<dim3(NS / 64, NB * NH), 256>>>();   // (16, 128)

    sgemm_nt<GM_PROJ><<<gg, 256>>>(nullptr, Wm, bm, y);

    ln_kernel<<<MROWS, 256>>>(a2, b2, out);
}

// round 5
// speedup vs baseline: 3.4769x; 3.4769x over previous
#include <cuda_runtime.h>

// Problem constants
#define NB   8
#define NS   1024
#define ND   1024
#define NH   16
#define NHD  64
#define MROWS (NB * NS)   // 8192

// ---------------------------------------------------------------------------
// Device scratch (allocation-free rule: __device__ globals)
// ---------------------------------------------------------------------------
__device__ float g_q[(size_t)MROWS * ND];
__device__ float g_k[(size_t)MROWS * ND];
__device__ float g_v[(size_t)MROWS * ND];
__device__ float g_o[(size_t)MROWS * ND];
__device__ float g_x[(size_t)MROWS * ND];
__device__ float g_bias[MROWS];           // additive mask bias per (b, key)

// ---------------------------------------------------------------------------
// tf32 helpers
// ---------------------------------------------------------------------------
__device__ __forceinline__ unsigned f2tf(float x) {
    unsigned u;
    asm("cvt.rna.tf32.f32 %0, %1;" : "=r"(u) : "f"(x));
    return u;
}

// D = A(16x8) * B(8x8) + D, tf32 inputs, fp32 accum.
__device__ __forceinline__ void mma_tf32(float* d, const unsigned* a, const unsigned* b) {
    asm volatile(
        "mma.sync.aligned.m16n8k8.row.col.f32.tf32.tf32.f32 "
        "{%0,%1,%2,%3}, {%4,%5,%6,%7}, {%8,%9}, {%0,%1,%2,%3};\n"
        : "+f"(d[0]), "+f"(d[1]), "+f"(d[2]), "+f"(d[3])
        : "r"(a[0]), "r"(a[1]), "r"(a[2]), "r"(a[3]), "r"(b[0]), "r"(b[1]));
}

// ---------------------------------------------------------------------------
// Mask conversion: robust to int32 / float32 / byte-bool encodings.
// ---------------------------------------------------------------------------
__global__ void mask_convert(const void* __restrict__ mask) {
    __shared__ int flag_not01;
    __shared__ int flag_notfp;
    if (threadIdx.x == 0) { flag_not01 = 0; flag_notfp = 0; }
    __syncthreads();
    const unsigned* w = (const unsigned*)mask;
    for (int i = threadIdx.x; i < 2048; i += blockDim.x) {
        unsigned v = w[i];
        if (v > 1u) flag_not01 = 1;
        if (v != 0u && v != 0x3F800000u) flag_notfp = 1;
    }
    __syncthreads();
    const int mode = (flag_not01 == 0) ? 0 : ((flag_notfp == 0) ? 1 : 2);
    for (int i = threadIdx.x; i < MROWS; i += blockDim.x) {
        bool on;
        if (mode == 0)      on = ((const int*)mask)[i] != 0;
        else if (mode == 1) on = ((const float*)mask)[i] != 0.0f;
        else                on = ((const unsigned char*)mask)[i] != 0;
        g_bias[i] = on ? -1e9f : 0.0f;
    }
}

// ---------------------------------------------------------------------------
// tf32 GEMM (NT): C[m,n] = sum_k A[m,k]*W[n,k] + bias[n] (+ res[m,n])
// CTA 128x128, k-chunk 32. 8 warps in 2(m) x 4(n); warp tile 64x32.
// Smem stride 36 floats => fragment LDS banks (4g+t+const) conflict-free.
// ---------------------------------------------------------------------------
#define GM_TO_Q 0
#define GM_TO_K 1
#define GM_TO_V 2
#define GM_PROJ 3

template <int MODE>
__global__ __launch_bounds__(256, 2) void gemm_tf32(
    const float* __restrict__ Ain, const float* __restrict__ W,
    const float* __restrict__ bias, const float* __restrict__ res_y)
{
    const float* A = (MODE == GM_PROJ) ? g_o : Ain;
    float* C = (MODE == GM_TO_Q) ? g_q
             : (MODE == GM_TO_K) ? g_k
             : (MODE == GM_TO_V) ? g_v : g_x;

    __shared__ unsigned As[128 * 36];
    __shared__ unsigned Bs[128 * 36];

    const int tid  = threadIdx.x;
    const int warp = tid >> 5, lane = tid & 31;
    const int g = lane >> 2, t = lane & 3;
    const int wm = warp & 1, wn = warp >> 1;
    const int row0 = blockIdx.y * 128;
    const int col0 = blockIdx.x * 128;

    const int lrow = tid >> 1;
    const int lcol = (tid & 1) << 4;
    const float* ap = A + (size_t)(row0 + lrow) * ND + lcol;
    const float* bp = W + (size_t)(col0 + lrow) * ND + lcol;

    float4 pa[4], pb[4];
#pragma unroll
    for (int i = 0; i < 4; ++i) {
        pa[i] = *(const float4*)(ap + 4 * i);
        pb[i] = *(const float4*)(bp + 4 * i);
    }

    float acc[4][4][4];
#pragma unroll
    for (int mt = 0; mt < 4; ++mt)
#pragma unroll
        for (int nt = 0; nt < 4; ++nt)
#pragma unroll
            for (int j = 0; j < 4; ++j) acc[mt][nt][j] = 0.0f;

    unsigned* asw = &As[lrow * 36 + lcol];
    unsigned* bsw = &Bs[lrow * 36 + lcol];

#pragma unroll 1
    for (int kc = 0; kc < 32; ++kc) {
#pragma unroll
        for (int i = 0; i < 4; ++i) {
            uint4 ua = make_uint4(f2tf(pa[i].x), f2tf(pa[i].y), f2tf(pa[i].z), f2tf(pa[i].w));
            *(uint4*)(asw + 4 * i) = ua;
            uint4 ub = make_uint4(f2tf(pb[i].x), f2tf(pb[i].y), f2tf(pb[i].z), f2tf(pb[i].w));
            *(uint4*)(bsw + 4 * i) = ub;
        }
        __syncthreads();
        if (kc < 31) {
            ap += 32; bp += 32;
#pragma unroll
            for (int i = 0; i < 4; ++i) {
                pa[i] = *(const float4*)(ap + 4 * i);
                pb[i] = *(const float4*)(bp + 4 * i);
            }
        }
#pragma unroll
        for (int ks = 0; ks < 4; ++ks) {
            unsigned af[4][4], bf[4][2];
#pragma unroll
            for (int mt = 0; mt < 4; ++mt) {
                const unsigned* p = &As[(wm * 64 + mt * 16 + g) * 36 + ks * 8 + t];
                af[mt][0] = p[0];
                af[mt][1] = p[8 * 36];
                af[mt][2] = p[4];
                af[mt][3] = p[8 * 36 + 4];
            }
#pragma unroll
            for (int nt = 0; nt < 4; ++nt) {
                const unsigned* p = &Bs[(wn * 32 + nt * 8 + g) * 36 + ks * 8 + t];
                bf[nt][0] = p[0];
                bf[nt][1] = p[4];
            }
#pragma unroll
            for (int mt = 0; mt < 4; ++mt)
#pragma unroll
                for (int nt = 0; nt < 4; ++nt)
                    mma_tf32(acc[mt][nt], af[mt], bf[nt]);
        }
        __syncthreads();
    }

    // Epilogue: bias (+ residual), float2 stores (cols 2t, 2t+1)
#pragma unroll
    for (int nt = 0; nt < 4; ++nt) {
        const int c = col0 + wn * 32 + nt * 8 + 2 * t;
        const float2 bb = *(const float2*)&bias[c];
#pragma unroll
        for (int mt = 0; mt < 4; ++mt) {
            const int r = row0 + wm * 64 + mt * 16 + g;
            float2 o0 = make_float2(acc[mt][nt][0] + bb.x, acc[mt][nt][1] + bb.y);
            float2 o1 = make_float2(acc[mt][nt][2] + bb.x, acc[mt][nt][3] + bb.y);
            if (MODE == GM_PROJ) {
                const float2 r0v = *(const float2*)&res_y[(size_t)r * ND + c];
                const float2 r1v = *(const float2*)&res_y[(size_t)(r + 8) * ND + c];
                o0.x += r0v.x; o0.y += r0v.y;
                o1.x += r1v.x; o1.y += r1v.y;
            }
            *(float2*)&C[(size_t)r * ND + c]       = o0;
            *(float2*)&C[(size_t)(r + 8) * ND + c] = o1;
        }
    }
}

// ---------------------------------------------------------------------------
// Flash attention, tf32 mma. CTA = 128 q-rows x 1 head. 8 warps; warp owns a
// 16-row band. Q fragments live in registers for the whole kernel. BN=32 K/V
// chunks. Softmax stats computed in fragments via shfl (lanes 4g+t => xor 1,2
// reduce within a row). P goes through smem only to relayout into A-fragments
// (own-warp rows => __syncwarp suffices).
// ---------------------------------------------------------------------------
__global__ __launch_bounds__(256, 2) void attn_mma()
{
    __shared__ unsigned Ks[32 * 68];   // [key][hd], stride 68: S-mma B-frags conflict-free
    __shared__ unsigned Vs[32 * 72];   // [key][hd], stride 72: PV B-frags conflict-free
    __shared__ unsigned Ps[128 * 36];  // [qrow][key-in-chunk] tf32 probabilities

    const int tid  = threadIdx.x;
    const int warp = tid >> 5, lane = tid & 31;
    const int g = lane >> 2, t = lane & 3;
    const int b  = blockIdx.y >> 4;
    const int h  = blockIdx.y & 15;
    const int q0 = blockIdx.x << 7;

    // Q fragments (scaled by 1/sqrt(HD) = 0.125), rows warp*16+g and +8
    unsigned qf[8][4];
    {
        const int r0 = b * NS + q0 + warp * 16 + g;
        const float* qp  = g_q + ((size_t)r0 << 10) + (h << 6);
        const float* qp8 = qp + ((size_t)8 << 10);
#pragma unroll
        for (int ks = 0; ks < 8; ++ks) {
            const int c = ks * 8 + t;
            qf[ks][0] = f2tf(qp[c] * 0.125f);
            qf[ks][1] = f2tf(qp8[c] * 0.125f);
            qf[ks][2] = f2tf(qp[c + 4] * 0.125f);
            qf[ks][3] = f2tf(qp8[c + 4] * 0.125f);
        }
    }

    float of[8][4];
#pragma unroll
    for (int nt = 0; nt < 8; ++nt)
#pragma unroll
        for (int j = 0; j < 4; ++j) of[nt][j] = 0.0f;
    float m0 = -1e30f, m1 = -1e30f, l0 = 0.0f, l1 = 0.0f;

    const size_t kvbase = ((size_t)b << 20) + (size_t)(h << 6);
    const int key = tid >> 3;           // loader: key row 0..31
    const int cb  = (tid & 7) << 3;     // loader: 8-float column chunk

#pragma unroll 1
    for (int kc = 0; kc < 32; ++kc) {
        const int key0 = kc << 5;
        __syncthreads();   // prev chunk's PV reads of Vs/Ps done before overwrite
        {
            const float* kp = g_k + kvbase + ((size_t)(key0 + key) << 10) + cb;
            const float* vp = g_v + kvbase + ((size_t)(key0 + key) << 10) + cb;
            const float4 k1 = *(const float4*)kp;
            const float4 k2 = *(const float4*)(kp + 4);
            const float4 v1 = *(const float4*)vp;
            const float4 v2 = *(const float4*)(vp + 4);
            unsigned* kd = &Ks[key * 68 + cb];
            unsigned* vd = &Vs[key * 72 + cb];
            *(uint4*)kd       = make_uint4(f2tf(k1.x), f2tf(k1.y), f2tf(k1.z), f2tf(k1.w));
            *(uint4*)(kd + 4) = make_uint4(f2tf(k2.x), f2tf(k2.y), f2tf(k2.z), f2tf(k2.w));
            *(uint4*)vd       = make_uint4(f2tf(v1.x), f2tf(v1.y), f2tf(v1.z), f2tf(v1.w));
            *(uint4*)(vd + 4) = make_uint4(f2tf(v2.x), f2tf(v2.y), f2tf(v2.z), f2tf(v2.w));
        }
        __syncthreads();

        // S = Q @ K^T : warp band 16 x 32, 4 n-tiles, 8 k-steps
        float sf[4][4];
#pragma unroll
        for (int nt = 0; nt < 4; ++nt)
#pragma unroll
            for (int j = 0; j < 4; ++j) sf[nt][j] = 0.0f;
#pragma unroll
        for (int ks = 0; ks < 8; ++ks) {
#pragma unroll
            for (int nt = 0; nt < 4; ++nt) {
                unsigned bf[2];
                const unsigned* p = &Ks[(nt * 8 + g) * 68 + ks * 8 + t];
                bf[0] = p[0];
                bf[1] = p[4];
                mma_tf32(sf[nt], qf[ks], bf);
            }
        }

        // mask bias (cols nt*8 + 2t, 2t+1)
#pragma unroll
        for (int nt = 0; nt < 4; ++nt) {
            const float2 bb = *(const float2*)&g_bias[(b << 10) + key0 + nt * 8 + 2 * t];
            sf[nt][0] += bb.x; sf[nt][1] += bb.y;
            sf[nt][2] += bb.x; sf[nt][3] += bb.y;
        }

        // row max (rows g and g+8) across fragments + lanes t
        float mx0 = -1e30f, mx1 = -1e30f;
#pragma unroll
        for (int nt = 0; nt < 4; ++nt) {
            mx0 = fmaxf(mx0, fmaxf(sf[nt][0], sf[nt][1]));
            mx1 = fmaxf(mx1, fmaxf(sf[nt][2], sf[nt][3]));
        }
        mx0 = fmaxf(mx0, __shfl_xor_sync(0xffffffffu, mx0, 1));
        mx0 = fmaxf(mx0, __shfl_xor_sync(0xffffffffu, mx0, 2));
        mx1 = fmaxf(mx1, __shfl_xor_sync(0xffffffffu, mx1, 1));
        mx1 = fmaxf(mx1, __shfl_xor_sync(0xffffffffu, mx1, 2));

        const float nm0 = fmaxf(m0, mx0);
        const float nm1 = fmaxf(m1, mx1);
        const float al0 = __expf(m0 - nm0);
        const float al1 = __expf(m1 - nm1);

        float sum0 = 0.0f, sum1 = 0.0f;
#pragma unroll
        for (int nt = 0; nt < 4; ++nt) {
            sf[nt][0] = __expf(sf[nt][0] - nm0);
            sf[nt][1] = __expf(sf[nt][1] - nm0);
            sf[nt][2] = __expf(sf[nt][2] - nm1);
            sf[nt][3] = __expf(sf[nt][3] - nm1);
            sum0 += sf[nt][0] + sf[nt][1];
            sum1 += sf[nt][2] + sf[nt][3];
        }
        sum0 += __shfl_xor_sync(0xffffffffu, sum0, 1);
        sum0 += __shfl_xor_sync(0xffffffffu, sum0, 2);
        sum1 += __shfl_xor_sync(0xffffffffu, sum1, 1);
        sum1 += __shfl_xor_sync(0xffffffffu, sum1, 2);
        l0 = l0 * al0 + sum0;  m0 = nm0;
        l1 = l1 * al1 + sum1;  m1 = nm1;

        // write P fragments (tf32) to own-warp smem rows
        {
            const int pr = warp * 16 + g;
#pragma unroll
            for (int nt = 0; nt < 4; ++nt) {
                const int c = nt * 8 + 2 * t;
                Ps[pr * 36 + c]           = f2tf(sf[nt][0]);
                Ps[pr * 36 + c + 1]       = f2tf(sf[nt][1]);
                Ps[(pr + 8) * 36 + c]     = f2tf(sf[nt][2]);
                Ps[(pr + 8) * 36 + c + 1] = f2tf(sf[nt][3]);
            }
        }
        __syncwarp();

        // O = O*alpha + P @ V  (8 n-tiles of hd, 4 k-tiles of keys)
#pragma unroll
        for (int nt = 0; nt < 8; ++nt) {
            of[nt][0] *= al0; of[nt][1] *= al0;
            of[nt][2] *= al1; of[nt][3] *= al1;
        }
#pragma unroll
        for (int kt = 0; kt < 4; ++kt) {
            unsigned af[4];
            const unsigned* p = &Ps[(warp * 16 + g) * 36 + kt * 8 + t];
            af[0] = p[0];
            af[1] = p[8 * 36];
            af[2] = p[4];
            af[3] = p[8 * 36 + 4];
#pragma unroll
            for (int nt = 0; nt < 8; ++nt) {
                unsigned bf[2];
                bf[0] = Vs[(kt * 8 + t) * 72 + nt * 8 + g];
                bf[1] = Vs[(kt * 8 + t + 4) * 72 + nt * 8 + g];
                mma_tf32(of[nt], af, bf);
            }
        }
    }

    // finalize: divide by l, store (cols h*64 + nt*8 + 2t)
    const float r0i = 1.0f / l0;
    const float r1i = 1.0f / l1;
    float* op  = g_o + ((size_t)(b * NS + q0 + warp * 16 + g) << 10) + (h << 6);
    float* op8 = op + ((size_t)8 << 10);
#pragma unroll
    for (int nt = 0; nt < 8; ++nt) {
        const int c = nt * 8 + 2 * t;
        *(float2*)&op[c]  = make_float2(of[nt][0] * r0i, of[nt][1] * r0i);
        *(float2*)&op8[c] = make_float2(of[nt][2] * r1i, of[nt][3] * r1i);
    }
}

// ---------------------------------------------------------------------------
// LayerNorm (torch semantics): unbiased std (ddof=1), eps added to std.
// ---------------------------------------------------------------------------
__global__ __launch_bounds__(256) void ln_kernel(
    const float* __restrict__ a2, const float* __restrict__ b2,
    float* __restrict__ out)
{
    const int row = blockIdx.x;
    const int tid = threadIdx.x;
    const float* xr = g_x + (size_t)row * ND;
    const float4 v = *(const float4*)(xr + 4 * tid);

    float s  = v.x + v.y + v.z + v.w;
    float sq = v.x * v.x + v.y * v.y + v.z * v.z + v.w * v.w;
#pragma unroll
    for (int o = 16; o > 0; o >>= 1) {
        s  += __shfl_xor_sync(0xffffffffu, s, o);
        sq += __shfl_xor_sync(0xffffffffu, sq, o);
    }
    __shared__ float sh_s[8], sh_q[8];
    const int w = tid >> 5, ln = tid & 31;
    if (ln == 0) { sh_s[w] = s; sh_q[w] = sq; }
    __syncthreads();
    if (w == 0) {
        s  = (ln < 8) ? sh_s[ln] : 0.0f;
        sq = (ln < 8) ? sh_q[ln] : 0.0f;
#pragma unroll
        for (int o = 4; o > 0; o >>= 1) {
            s  += __shfl_xor_sync(0xffffffffu, s, o);
            sq += __shfl_xor_sync(0xffffffffu, sq, o);
        }
        if (ln == 0) { sh_s[0] = s; sh_q[0] = sq; }
    }
    __syncthreads();
    s  = sh_s[0];
    sq = sh_q[0];

    const float mean = s * (1.0f / 1024.0f);
    const float var  = (sq - s * mean) * (1.0f / 1023.0f);
    const float inv  = 1.0f / (sqrtf(fmaxf(var, 0.0f)) + 1e-6f);

    const float4 av = *(const float4*)(a2 + 4 * tid);
    const float4 bv = *(const float4*)(b2 + 4 * tid);
    float4 o;
    o.x = av.x * (v.x - mean) * inv + bv.x;
    o.y = av.y * (v.y - mean) * inv + bv.y;
    o.z = av.z * (v.z - mean) * inv + bv.z;
    o.w = av.w * (v.w - mean) * inv + bv.w;
    *(float4*)(out + (size_t)row * ND + 4 * tid) = o;
}

// ---------------------------------------------------------------------------
// Launch
// ---------------------------------------------------------------------------
extern "C" void kernel_launch(void* const* d_in, const int* in_sizes, int n_in,
                              void* d_out, int out_size)
{
    const float* y  = (const float*)d_in[0];
    const void*  mk = d_in[1];
    const float* Wq = (const float*)d_in[2];
    const float* bq = (const float*)d_in[3];
    const float* Wk = (const float*)d_in[4];
    const float* bk = (const float*)d_in[5];
    const float* Wv = (const float*)d_in[6];
    const float* bv = (const float*)d_in[7];
    const float* Wm = (const float*)d_in[8];
    const float* bm = (const float*)d_in[9];
    const float* a2 = (const float*)d_in[10];
    const float* b2 = (const float*)d_in[11];
    float* out = (float*)d_out;

    mask_convert<<<1, 256>>>(mk);

    const dim3 gg(ND / 128, MROWS / 128);   // (8, 64)
    gemm_tf32<GM_TO_Q><<<gg, 256>>>(y, Wq, bq, nullptr);
    gemm_tf32<GM_TO_K><<<gg, 256>>>(y, Wk, bk, nullptr);
    gemm_tf32<GM_TO_V><<<gg, 256>>>(y, Wv, bv, nullptr);

    attn_mma<<<dim3(NS / 128, NB * NH), 256>>>();   // (8, 128)

    gemm_tf32<GM_PROJ><<<gg, 256>>>(nullptr, Wm, bm, y);

    ln_kernel<<<MROWS, 256>>>(a2, b2, out);
}